// round 16
// baseline (speedup 1.0000x reference)
#include <cuda_runtime.h>
#include <cuda_fp16.h>
#include <cstdint>
#include <math.h>

#define NB 8
#define CIN 256
#define HWSZ 16384
#define OCB 256
#define NCLS 18
#define NREG 36
#define NTOT 54
#define BNEPS 1e-5f
#define NT 32768        // total 2x2 output tiles (8 imgs * 64*64)

// ---------------- scratch (device globals) ----------------
__device__ __half sc_V[(size_t)8 * 16 * NT * 32];   // [ch][xi][t][32ci perm+swz]  268MB
__device__ __half sc_U[(size_t)8 * 16 * 256 * 32];  // [ch][xi][oc][32ci perm+swz] 2MB
__device__ __half sc_base[(size_t)NB * OCB * HWSZ]; // conv+mish output NCHW (fp16)
__device__ float sc_part[256][1024][2];             // per-CTA BN partials
__device__ float sc_cls[(size_t)NB * NCLS * HWSZ];
__device__ float sc_reg[(size_t)NB * NREG * HWSZ];
__device__ float sc_scaleA[CIN];
__device__ float sc_shiftA[CIN];
__device__ float sc_Wf[NTOT * CIN];
__device__ float sc_bf[NTOT];
__device__ float sc_s2[NTOT];
__device__ float sc_h2[NTOT];

// ---------------- helpers ----------------
__device__ __forceinline__ uint32_t smem_u32(const void* p) {
    return (uint32_t)__cvta_generic_to_shared(p);
}
__device__ __forceinline__ unsigned long long pk2(float v) {
    unsigned long long r; unsigned u = __float_as_uint(v);
    asm("mov.b64 %0, {%1, %2};" : "=l"(r) : "r"(u), "r"(u));
    return r;
}
__device__ __forceinline__ unsigned long long pk2ab(float a, float b) {
    unsigned long long r;
    asm("mov.b64 %0, {%1, %2};" : "=l"(r) : "r"(__float_as_uint(a)), "r"(__float_as_uint(b)));
    return r;
}
__device__ __forceinline__ void fma2(unsigned long long& d, unsigned long long a, unsigned long long b) {
    asm("fma.rn.f32x2 %0, %1, %2, %0;" : "+l"(d) : "l"(a), "l"(b));
}
__device__ __forceinline__ float2 upk(unsigned long long v) {
    unsigned lo, hi;
    asm("mov.b64 {%0, %1}, %2;" : "=r"(lo), "=r"(hi) : "l"(v));
    return make_float2(__uint_as_float(lo), __uint_as_float(hi));
}
__device__ __forceinline__ float mishf(float v) {
    float sp = fmaxf(v, 0.f) + log1pf(expf(-fabsf(v)));
    return v * tanhf(sp);
}
__device__ __forceinline__ float block_reduce(float v, float* red, int tid) {
    red[tid] = v; __syncthreads();
#pragma unroll
    for (int o = 128; o > 0; o >>= 1) {
        if (tid < o) red[tid] += red[tid + o];
        __syncthreads();
    }
    float r = red[0];
    __syncthreads();
    return r;
}
__device__ __forceinline__ int pidx16(int k) {
    return (k < 8) ? ((k >> 1) * 4 + (k & 1)) : (((k - 8) >> 1) * 4 + 2 + (k & 1));
}
__device__ __forceinline__ int pidx32h(int a) {
    return (a & 16) + pidx16(a & 15);
}
__device__ __forceinline__ int swz(int p) {
    int t = (p >> 1) & 3;
    return t ^ ((t & 1) << 2);
}

#define MBAR_INIT(a, c) \
    asm volatile("mbarrier.init.shared.b64 [%0], %1;" :: "r"((uint32_t)(a)), "r"((uint32_t)(c)) : "memory")
#define MBAR_EXPECT(a, bytes) \
    asm volatile("mbarrier.arrive.expect_tx.shared.b64 _, [%0], %1;" :: "r"((uint32_t)(a)), "r"((uint32_t)(bytes)) : "memory")
#define MBAR_WAIT(a, p) do {                                                         \
    uint32_t _m = (uint32_t)(a), _p = (uint32_t)(p), _d;                             \
    asm volatile("{\n\t.reg .pred q;\n\t"                                            \
        "mbarrier.try_wait.parity.acquire.cta.shared::cta.b64 q, [%1], %2;\n\t"      \
        "selp.b32 %0, 1, 0, q;\n\t}" : "=r"(_d) : "r"(_m), "r"(_p) : "memory");      \
    if (!_d) {                                                                       \
        asm volatile("{\n\t.reg .pred Q;\n\tWL_%=:\n\t"                              \
            "mbarrier.try_wait.parity.acquire.cta.shared::cta.b64 Q, [%0], %1, 0x989680;\n\t" \
            "@Q bra.uni WD_%=;\n\tbra.uni WL_%=;\n\tWD_%=:\n\t}"                     \
            :: "r"(_m), "r"(_p) : "memory");                                         \
    }                                                                                \
} while (0)

__device__ __forceinline__ void bulk_cp(uint32_t dst, const void* src, uint32_t bytes, uint32_t mbar) {
    asm volatile(
        "cp.async.bulk.shared::cluster.global.mbarrier::complete_tx::bytes [%0], [%1], %2, [%3];"
        :: "r"(dst), "l"(src), "r"(bytes), "r"(mbar) : "memory");
}

// ---------------- kdummy: profiling alignment no-op ----------------
__global__ void kdummy() {}

// ---------------- kU: weight transform G g G^T -> U ----------------
__global__ void kU(const float* __restrict__ W) {
    int oc = blockIdx.x, ci = threadIdx.x;
    const float* g = W + ((size_t)oc * CIN + ci) * 9;
    float t4[4][3];
#pragma unroll
    for (int c = 0; c < 3; c++) {
        float g0 = g[c], g1 = g[3 + c], g2 = g[6 + c];
        t4[0][c] = g0;
        t4[1][c] = 0.5f * (g0 + g1 + g2);
        t4[2][c] = 0.5f * (g0 - g1 + g2);
        t4[3][c] = g2;
    }
    int ch = ci >> 5, p = pidx32h(ci & 31);
    int pos = ((p >> 2) ^ swz(oc & 7)) * 4 + (p & 3);
#pragma unroll
    for (int i = 0; i < 4; i++) {
        float u0 = t4[i][0];
        float u1 = 0.5f * (t4[i][0] + t4[i][1] + t4[i][2]);
        float u2 = 0.5f * (t4[i][0] - t4[i][1] + t4[i][2]);
        float u3 = t4[i][2];
        sc_U[(((size_t)ch * 16 + i * 4 + 0) * 256 + oc) * 32 + pos] = __float2half_rn(u0);
        sc_U[(((size_t)ch * 16 + i * 4 + 1) * 256 + oc) * 32 + pos] = __float2half_rn(u1);
        sc_U[(((size_t)ch * 16 + i * 4 + 2) * 256 + oc) * 32 + pos] = __float2half_rn(u2);
        sc_U[(((size_t)ch * 16 + i * 4 + 3) * 256 + oc) * 32 + pos] = __float2half_rn(u3);
    }
}

// ---------------- kV: input transform B^T d B -> V, 4 tile-rows per CTA ----------------
// xs [ci32][10r][66c] fp32 (84480B) + vs [xi16][t32][36] fp16 (36864B)
#define KV_SMEM 121344
__global__ void kV(const float* __restrict__ x) {
    extern __shared__ float dsm[];
    float* xs = dsm;                      // [ci32][10r][66c]
    __half* vs = (__half*)(dsm + 21120); // [xi16][t32][36 pad]
    int bx = blockIdx.x;
    int ch = bx >> 1, txs = bx & 1;
    int tyg = blockIdx.y, n = blockIdx.z;
    int tid = threadIdx.x;
    int gy0 = 8 * tyg - 1, gx0 = txs * 64 - 1;
    for (int i = tid; i < 21120; i += 256) {
        int col = i % 66;
        int rest = i / 66;           // ci*10 + r
        int r = rest % 10, ci = rest / 10;
        int gy = gy0 + r, gx = gx0 + col;
        float v = 0.f;
        if ((unsigned)gy < 128u && (unsigned)gx < 128u)
            v = x[((size_t)(n * CIN + ch * 32 + ci)) * HWSZ + gy * 128 + gx];
        xs[i] = v;
    }
    __syncthreads();
#pragma unroll 1
    for (int tr = 0; tr < 4; tr++) {
        if (tr) __syncthreads();   // vs copy-out of previous tr complete
#pragma unroll
        for (int u = 0; u < 4; u++) {
            int pr = tid + u * 256;
            int tx = pr & 31, ci = pr >> 5;
            const float* bp = xs + (ci * 10 + 2 * tr) * 66 + 2 * tx;
            float d[4][4];
#pragma unroll
            for (int r = 0; r < 4; r++)
#pragma unroll
                for (int c = 0; c < 4; c++) d[r][c] = bp[r * 66 + c];
            float t4[4][4];
#pragma unroll
            for (int c = 0; c < 4; c++) {
                t4[0][c] = d[0][c] - d[2][c];
                t4[1][c] = d[1][c] + d[2][c];
                t4[2][c] = d[2][c] - d[1][c];
                t4[3][c] = d[1][c] - d[3][c];
            }
            int p = pidx32h(ci);
            int pos = ((p >> 2) ^ swz(tx & 7)) * 4 + (p & 3);
#pragma unroll
            for (int i2 = 0; i2 < 4; i2++) {
                vs[((i2 * 4 + 0) * 32 + tx) * 36 + pos] = __float2half_rn(t4[i2][0] - t4[i2][2]);
                vs[((i2 * 4 + 1) * 32 + tx) * 36 + pos] = __float2half_rn(t4[i2][1] + t4[i2][2]);
                vs[((i2 * 4 + 2) * 32 + tx) * 36 + pos] = __float2half_rn(t4[i2][2] - t4[i2][1]);
                vs[((i2 * 4 + 3) * 32 + tx) * 36 + pos] = __float2half_rn(t4[i2][1] - t4[i2][3]);
            }
        }
        __syncthreads();
        int tg0 = n * 4096 + (tyg * 4 + tr) * 64 + txs * 32;
        for (int i = tid; i < 4096; i += 256) {
            int xi = i >> 8, rem = i & 255, t = rem >> 3, q = rem & 7;
            uint2 val = *(const uint2*)((const char*)vs + (xi * 32 + t) * 72 + q * 8);
            *((uint2*)(sc_V + (((size_t)ch * 16 + xi) * NT + tg0 + t) * 32) + q) = val;
        }
    }
}

// ---------------- kG: 16 xi-GEMMs, 4-deep pipeline + fused output transform ----------------
#define GST_H 24576
#define GST_B 49152u
#define G_MBAR 196608u
#define G_SMEM (196608 + 32)

__device__ __forceinline__ void g_issue(int ch, int g, int t0, int oc0,
                                        uint32_t smbase, int buf, uint32_t mbar) {
    MBAR_EXPECT(mbar, GST_B);
    uint32_t dst = smbase + (uint32_t)buf * GST_B;
#pragma unroll
    for (int q = 0; q < 8; q++) {
        int xi = g * 8 + q;
        bulk_cp(dst + q * 2048u, sc_V + (((size_t)ch * 16 + xi) * NT + t0) * 32, 2048u, mbar);
        bulk_cp(dst + 16384u + q * 4096u,
                sc_U + (((size_t)ch * 16 + xi) * 256 + oc0) * 32, 4096u, mbar);
    }
}

__device__ __forceinline__ void g_compute(const __half* A, const __half* Bp,
                                          float (&acc)[2][8][4], int mrow, int kc, int xsw) {
#pragma unroll
    for (int ks = 0; ks < 2; ks++) {
        int e = ((ks * 4 + kc) ^ xsw) * 4;
        uint32_t af[2][4];
#pragma unroll
        for (int mf = 0; mf < 2; mf++) {
            const __half* pa = A + (mf * 16 + mrow) * 32 + e;
            uint2 lo = *(const uint2*)pa;
            uint2 hi = *(const uint2*)(pa + 256);
            af[mf][0] = lo.x; af[mf][1] = hi.x; af[mf][2] = lo.y; af[mf][3] = hi.y;
        }
#pragma unroll
        for (int nf = 0; nf < 8; nf++) {
            uint2 bv = *(const uint2*)(Bp + (nf * 8 + mrow) * 32 + e);
#pragma unroll
            for (int mf = 0; mf < 2; mf++)
                asm volatile(
                    "mma.sync.aligned.m16n8k16.row.col.f32.f16.f16.f32 "
                    "{%0,%1,%2,%3}, {%4,%5,%6,%7}, {%8,%9}, {%0,%1,%2,%3};"
                    : "+f"(acc[mf][nf][0]), "+f"(acc[mf][nf][1]),
                      "+f"(acc[mf][nf][2]), "+f"(acc[mf][nf][3])
                    : "r"(af[mf][0]), "r"(af[mf][1]), "r"(af[mf][2]), "r"(af[mf][3]),
                      "r"(bv.x), "r"(bv.y));
        }
    }
}

__global__ void __launch_bounds__(256, 1) kG(const float* __restrict__ pb) {
    extern __shared__ __half smh[];
    uint32_t smbase = smem_u32(smh);
    int tid = threadIdx.x, lane = tid & 31, wid = tid >> 5;
    int ocb = blockIdx.x, tblk = blockIdx.y;
    int t0 = tblk * 32, oc0 = ocb * 64;
    int mrow = lane >> 2, kc = lane & 3, xsw = swz(mrow);

    float acc0[2][8][4], acc1[2][8][4];
#pragma unroll
    for (int a = 0; a < 2; a++)
#pragma unroll
        for (int b = 0; b < 8; b++)
#pragma unroll
            for (int c = 0; c < 4; c++) { acc0[a][b][c] = 0.f; acc1[a][b][c] = 0.f; }

    uint32_t mb = smbase + G_MBAR;
    if (tid == 0) {
        MBAR_INIT(mb, 1);
        MBAR_INIT(mb + 8, 1);
        MBAR_INIT(mb + 16, 1);
        MBAR_INIT(mb + 24, 1);
    }
    __syncthreads();
    if (tid == 0) {
#pragma unroll
        for (int b = 0; b < 4; b++)
            g_issue(b >> 1, b & 1, t0, oc0, smbase, b, mb + b * 8);
    }

#pragma unroll 1
    for (int st = 0; st < 16; st++) {
        int buf = st & 3;
        MBAR_WAIT(mb + buf * 8, (st >> 2) & 1);
        const __half* A = smh + buf * GST_H + wid * 1024;
        const __half* Bp = smh + buf * GST_H + 8192 + wid * 2048;
        if (st & 1) g_compute(A, Bp, acc1, mrow, kc, xsw);
        else g_compute(A, Bp, acc0, mrow, kc, xsw);
        __syncthreads();
        if (st + 4 < 16 && tid == 0)
            g_issue((st + 4) >> 1, (st + 4) & 1, t0, oc0, smbase, buf, mb + buf * 8);
    }

    // ---- fused epilogue: A^T M A + bias + mish + fp16 NCHW store + BN partials ----
    float* Ms = (float*)smh;          // [16xi][32t][8oc]
    float* ps = (float*)smh + 4096;   // [8r][32t][8oc][2]
    int nimg = t0 >> 12, rem = t0 & 4095;
    int ty2 = ((rem >> 6)) * 2, tx0 = rem & 63;
    int tl = tid >> 3, ocl = tid & 7;
#pragma unroll
    for (int r = 0; r < 8; r++) {
        __syncthreads();
#pragma unroll
        for (int mf = 0; mf < 2; mf++) {
            float* q0 = &Ms[((wid) * 32 + mf * 16 + mrow) * 8 + 2 * kc];
            q0[0] = acc0[mf][r][0]; q0[1] = acc0[mf][r][1];
            q0[64] = acc0[mf][r][2]; q0[65] = acc0[mf][r][3];
            float* q1 = &Ms[((8 + wid) * 32 + mf * 16 + mrow) * 8 + 2 * kc];
            q1[0] = acc1[mf][r][0]; q1[1] = acc1[mf][r][1];
            q1[64] = acc1[mf][r][2]; q1[65] = acc1[mf][r][3];
        }
        __syncthreads();
        float m[16];
#pragma unroll
        for (int xi = 0; xi < 16; xi++) m[xi] = Ms[(xi * 32 + tl) * 8 + ocl];
        float ta[2][4];
#pragma unroll
        for (int c = 0; c < 4; c++) {
            ta[0][c] = m[c] + m[4 + c] + m[8 + c];
            ta[1][c] = m[4 + c] - m[8 + c] - m[12 + c];
        }
        int oc = oc0 + r * 8 + ocl;
        float bv = pb[oc];
        float o00 = mishf(ta[0][0] + ta[0][1] + ta[0][2] + bv);
        float o01 = mishf(ta[0][1] - ta[0][2] - ta[0][3] + bv);
        float o10 = mishf(ta[1][0] + ta[1][1] + ta[1][2] + bv);
        float o11 = mishf(ta[1][1] - ta[1][2] - ta[1][3] + bv);
        __half* op = sc_base + ((size_t)(nimg * OCB + oc)) * HWSZ + ty2 * 128 + (tx0 + tl) * 2;
        *(__half2*)op = __floats2half2_rn(o00, o01);
        *(__half2*)(op + 128) = __floats2half2_rn(o10, o11);
        ps[((r * 32 + tl) * 8 + ocl) * 2 + 0] = o00 + o01 + o10 + o11;
        ps[((r * 32 + tl) * 8 + ocl) * 2 + 1] = o00 * o00 + o01 * o01 + o10 * o10 + o11 * o11;
    }
    __syncthreads();
    if (tid < 128) {
        int r = tid >> 4, oz = (tid >> 1) & 7, v = tid & 1;
        float s = 0.f;
        for (int t = 0; t < 32; t++) s += ps[((r * 32 + t) * 8 + oz) * 2 + v];
        sc_part[oc0 + r * 8 + oz][tblk][v] = s;
    }
}

// ---------------- K2: base BN stats from 1024 partials ----------------
__global__ void k2_base_stats(const float* __restrict__ gam, const float* __restrict__ bet) {
    __shared__ float red[256];
    int c = blockIdx.x, tid = threadIdx.x;
    float s = 0.f, q = 0.f;
    for (int i = tid; i < 1024; i += 256) { s += sc_part[c][i][0]; q += sc_part[c][i][1]; }
    float sum = block_reduce(s, red, tid);
    float sq = block_reduce(q, red, tid);
    if (tid == 0) {
        float inv_n = 1.f / (float)(NB * HWSZ);
        float mean = sum * inv_n;
        float var = sq * inv_n - mean * mean;
        float inv = rsqrtf(var + BNEPS);
        float scl = gam[c] * inv;
        sc_scaleA[c] = scl;
        sc_shiftA[c] = bet[c] - mean * scl;
    }
}

// ---------------- K3: fold base BN into 1x1 conv weights ----------------
__global__ void k3_fold(const float* __restrict__ Wc, const float* __restrict__ bc,
                        const float* __restrict__ Wr, const float* __restrict__ br) {
    __shared__ float red[256];
    int o = blockIdx.x, ci = threadIdx.x;
    const float* Ws;
    float bs;
    int ol;
    if (o < NCLS) { Ws = Wc; ol = o; bs = bc[o]; }
    else { Ws = Wr; ol = o - NCLS; bs = br[ol]; }
    float w = Ws[ol * CIN + ci];
    sc_Wf[o * CIN + ci] = w * sc_scaleA[ci];
    float tot = block_reduce(w * sc_shiftA[ci], red, ci);
    if (ci == 0) sc_bf[o] = bs + tot;
}

// ---------------- K4m: merged 1x1 convs (cls+reg), fp16 reads, adjacent px ----------------
#define K4_SMEM (CIN * 56 * 4)
__global__ void __launch_bounds__(256) k4m() {
    extern __shared__ float swf[];
    int tid = threadIdx.x;
    for (int i = tid; i < CIN * 56; i += 256) {
        int c = i / 56, o = i - c * 56;
        swf[i] = (o < NTOT) ? sc_Wf[o * CIN + c] : 0.f;
    }
    __syncthreads();
    int pstart = blockIdx.x * 512;
    int n = pstart >> 14;
    int hw2 = (pstart & 16383) + 2 * tid;

    unsigned long long acc2[27][2];
#pragma unroll
    for (int op = 0; op < 27; op++) {
        unsigned long long b = pk2ab(sc_bf[2 * op], sc_bf[2 * op + 1]);
        acc2[op][0] = b;
        acc2[op][1] = b;
    }
    const __half* bpn = sc_base + (size_t)n * OCB * HWSZ + hw2;
#pragma unroll 1
    for (int c = 0; c < CIN; c += 8) {
        float2 f[8];
#pragma unroll
        for (int u = 0; u < 8; u++) {
            __half2 h = *(const __half2*)(bpn + (size_t)(c + u) * HWSZ);
            f[u] = __half22float2(h);
        }
#pragma unroll
        for (int u = 0; u < 8; u++) {
            unsigned long long p0 = pk2(f[u].x), p1 = pk2(f[u].y);
            const unsigned long long* wrow = (const unsigned long long*)(swf + (c + u) * 56);
#pragma unroll
            for (int op = 0; op < 27; op++) {
                unsigned long long w = wrow[op];
                fma2(acc2[op][0], w, p0);
                fma2(acc2[op][1], w, p1);
            }
        }
    }
#pragma unroll
    for (int op = 0; op < 27; op++) {
        float2 a = upk(acc2[op][0]);
        float2 b = upk(acc2[op][1]);
        int ch0 = 2 * op, ch1 = 2 * op + 1;
        if (ch0 < NCLS)
            *(float2*)(sc_cls + (size_t)(n * NCLS + ch0) * HWSZ + hw2) = make_float2(a.x, b.x);
        else
            *(float2*)(sc_reg + (size_t)(n * NREG + (ch0 - NCLS)) * HWSZ + hw2) = make_float2(a.x, b.x);
        if (ch1 < NCLS)
            *(float2*)(sc_cls + (size_t)(n * NCLS + ch1) * HWSZ + hw2) = make_float2(a.y, b.y);
        else
            *(float2*)(sc_reg + (size_t)(n * NREG + (ch1 - NCLS)) * HWSZ + hw2) = make_float2(a.y, b.y);
    }
}

// ---------------- K5: cls/reg BN stats ----------------
__global__ void k5_stats2(const float* __restrict__ gc, const float* __restrict__ bc,
                          const float* __restrict__ gr, const float* __restrict__ br) {
    __shared__ float red[256];
    int b = blockIdx.x, tid = threadIdx.x;
    const float* src;
    int nch, ch;
    float gam, bet;
    if (b < NCLS) { src = sc_cls; nch = NCLS; ch = b; gam = gc[ch]; bet = bc[ch]; }
    else { src = sc_reg; nch = NREG; ch = b - NCLS; gam = gr[ch]; bet = br[ch]; }
    float s = 0.f;
    for (int n = 0; n < NB; n++) {
        const float* p = &src[(size_t)(n * nch + ch) * HWSZ];
        for (int i = tid; i < HWSZ; i += 256) s += p[i];
    }
    float mean = block_reduce(s, red, tid) * (1.f / (NB * HWSZ));
    s = 0.f;
    for (int n = 0; n < NB; n++) {
        const float* p = &src[(size_t)(n * nch + ch) * HWSZ];
        for (int i = tid; i < HWSZ; i += 256) {
            float d = p[i] - mean;
            s += d * d;
        }
    }
    float var = block_reduce(s, red, tid) * (1.f / (NB * HWSZ));
    if (tid == 0) {
        float inv = rsqrtf(var + BNEPS);
        float scl = gam * inv;
        sc_s2[b] = scl;
        sc_h2[b] = bet - mean * scl;
    }
}

// ---------------- K6: softmax + anchor decode ----------------
__constant__ float c_wa[9] = {455.f, 911.f, 1823.f, 319.f, 639.f, 1279.f, 223.f, 447.f, 895.f};
__constant__ float c_ha[9] = {223.f, 447.f, 895.f, 319.f, 639.f, 1279.f, 447.f, 895.f, 1791.f};

__global__ void k6_decode(const int* __restrict__ imgsz, float* __restrict__ out) {
    int t = blockIdx.x * 256 + threadIdx.x;
    if (t >= NB * HWSZ) return;
    int n = t >> 14, hw = t & 16383;
    int hy = hw >> 7, wx = hw & 127;
    float lim = 2048.f;
    if (imgsz) {
        int iv = *imgsz;
        lim = (iv > 0 && iv < (1 << 24)) ? (float)iv : __int_as_float(iv);
    }
    float cls[NCLS], rg[NREG];
#pragma unroll
    for (int o = 0; o < NCLS; o++)
        cls[o] = sc_cls[(size_t)(n * NCLS + o) * HWSZ + hw] * sc_s2[o] + sc_h2[o];
#pragma unroll
    for (int o = 0; o < NREG; o++)
        rg[o] = sc_reg[(size_t)(n * NREG + o) * HWSZ + hw] * sc_s2[NCLS + o] + sc_h2[NCLS + o];

    const size_t K = (size_t)HWSZ * 9;
    float* fg = out;
    float* ts = out + (size_t)NB * K;
    float* ro = ts + (size_t)NB * K * 4;
    size_t kb = (size_t)n * K + (size_t)hw * 9;

    float cxa = 19.5f + 16.f * (float)wx;
    float cya = 19.5f + 16.f * (float)hy;
#pragma unroll
    for (int a = 0; a < 9; a++) {
        float wa = c_wa[a], ha = c_ha[a];
        float x1 = fminf(fmaxf(rg[a * 4 + 0] + (cxa - 0.5f * wa), 0.f), lim);
        float y1 = fminf(fmaxf(rg[a * 4 + 1] + (cya - 0.5f * ha), 0.f), lim);
        float x2 = fminf(fmaxf(rg[a * 4 + 2] + (cxa + 0.5f * wa), 0.f), lim);
        float y2 = fminf(fmaxf(rg[a * 4 + 3] + (cya + 0.5f * ha), 0.f), lim);
        float w = x2 - x1, h = y2 - y1;
        float cx = x1 + 0.5f * w, cy = y1 + 0.5f * h;
        float s0 = cls[a * 2], s1 = cls[a * 2 + 1];
        fg[kb + a] = 1.f / (1.f + expf(s0 - s1));
        size_t o4 = (kb + a) * 4;
        ts[o4 + 0] = (cx - cxa) / wa;
        ts[o4 + 1] = (cy - cya) / ha;
        ts[o4 + 2] = logf(fmaxf(w / wa, 1e-30f));
        ts[o4 + 3] = logf(fmaxf(h / ha, 1e-30f));
        ro[o4 + 0] = cx;
        ro[o4 + 1] = cy;
        ro[o4 + 2] = w;
        ro[o4 + 3] = h;
    }
}

// ---------------- launch ----------------
extern "C" void kernel_launch(void* const* d_in, const int* in_sizes, int n_in,
                              void* d_out, int out_size) {
    const float* x   = (const float*)d_in[0];
    const float* Wb  = (const float*)d_in[1];
    const float* bb  = (const float*)d_in[2];
    const float* gb  = (const float*)d_in[3];
    const float* beb = (const float*)d_in[4];
    const float* Wc  = (const float*)d_in[5];
    const float* bc  = (const float*)d_in[6];
    const float* gc  = (const float*)d_in[7];
    const float* bec = (const float*)d_in[8];
    const float* Wr  = (const float*)d_in[9];
    const float* br  = (const float*)d_in[10];
    const float* gr  = (const float*)d_in[11];
    const float* ber = (const float*)d_in[12];
    const int* imgsz = (n_in > 13) ? (const int*)d_in[13] : nullptr;
    float* out = (float*)d_out;

    static int smem_set = 0;
    if (!smem_set) {
        cudaFuncSetAttribute(kG, cudaFuncAttributeMaxDynamicSharedMemorySize, G_SMEM);
        cudaFuncSetAttribute(kV, cudaFuncAttributeMaxDynamicSharedMemorySize, KV_SMEM);
        cudaFuncSetAttribute(k4m, cudaFuncAttributeMaxDynamicSharedMemorySize, K4_SMEM);
        smem_set = 1;
    }

    kU<<<256, 256>>>(Wb);                            // launch 0
    kV<<<dim3(16, 16, NB), 256, KV_SMEM>>>(x);       // launch 1
    kdummy<<<1, 32>>>();                             // launch 2 (aligns ncu capture onto kG)
    kG<<<dim3(4, 1024), 256, G_SMEM>>>(bb);          // launch 3 <- profiled

    k2_base_stats<<<OCB, 256>>>(gb, beb);
    k3_fold<<<NTOT, 256>>>(Wc, bc, Wr, br);
    k4m<<<NB * HWSZ / 512, 256, K4_SMEM>>>();
    k5_stats2<<<NTOT, 256>>>(gc, bec, gr, ber);
    k6_decode<<<NB * HWSZ / 256, 256>>>(imgsz, out);
}

// round 17
// speedup vs baseline: 1.4985x; 1.4985x over previous
#include <cuda_runtime.h>
#include <cuda_fp16.h>
#include <cstdint>
#include <math.h>

#define NB 8
#define CIN 256
#define HH 128
#define WW 128
#define HWSZ 16384
#define OCB 256
#define NCLS 18
#define NREG 36
#define NTOT 54
#define BNEPS 1e-5f
#define PW 130          // padded H/W

// ---------------- scratch (device globals; zero-initialized at load) ----------------
// chunk-major padded input: [n][chunk 8][h 130][w 130][32 ci as 8B-units e'=swizzled]
__device__ __half sc_pad[(size_t)NB * 8 * PW * PW * 32];
// weights: [chunk 8][tap 9][oc 256][32 ci swizzled]
__device__ __half sc_Wp[8 * 9 * OCB * 32];
__device__ __half sc_base[(size_t)NB * OCB * HWSZ];    // conv3x3+mish output (pre-BN), NCHW fp16
__device__ float sc_part[256][512][2];                 // per-CTA (sum, sumsq) partials per channel
__device__ float sc_cls[(size_t)NB * NCLS * HWSZ];
__device__ float sc_reg[(size_t)NB * NREG * HWSZ];
__device__ float sc_scaleA[CIN];
__device__ float sc_shiftA[CIN];
__device__ float sc_Wf[NTOT * CIN];
__device__ float sc_bf[NTOT];
__device__ float sc_s2[NTOT];
__device__ float sc_h2[NTOT];

// ---------------- helpers ----------------
__device__ __forceinline__ uint32_t smem_u32(const void* p) {
    return (uint32_t)__cvta_generic_to_shared(p);
}
__device__ __forceinline__ unsigned long long pk2(float v) {
    unsigned long long r; unsigned u = __float_as_uint(v);
    asm("mov.b64 %0, {%1, %2};" : "=l"(r) : "r"(u), "r"(u));
    return r;
}
__device__ __forceinline__ unsigned long long pk2ab(float a, float b) {
    unsigned long long r;
    asm("mov.b64 %0, {%1, %2};" : "=l"(r) : "r"(__float_as_uint(a)), "r"(__float_as_uint(b)));
    return r;
}
__device__ __forceinline__ void fma2(unsigned long long& d, unsigned long long a, unsigned long long b) {
    asm("fma.rn.f32x2 %0, %1, %2, %0;" : "+l"(d) : "l"(a), "l"(b));
}
__device__ __forceinline__ float2 upk(unsigned long long v) {
    unsigned lo, hi;
    asm("mov.b64 {%0, %1}, %2;" : "=r"(lo), "=r"(hi) : "l"(v));
    return make_float2(__uint_as_float(lo), __uint_as_float(hi));
}
// exact identity: tanh(softplus(x)) = (s^2 + 2s) / (s^2 + 2s + 2), s = e^x
__device__ __forceinline__ float mishf(float v) {
    float s = __expf(v);
    float t = s * s + 2.f * s;
    float r = t / (t + 2.f);
    return (v > 15.f) ? v : v * r;
}
__device__ __forceinline__ float block_reduce(float v, float* red, int tid) {
    red[tid] = v; __syncthreads();
#pragma unroll
    for (int o = 128; o > 0; o >>= 1) {
        if (tid < o) red[tid] += red[tid + o];
        __syncthreads();
    }
    float r = red[0];
    __syncthreads();
    return r;
}
// within-16 permutation for m16n8k16 frags: (2kc,2kc+1,2kc+8,2kc+9) contiguous per kc
__device__ __forceinline__ int pidx16(int k) {
    return (k < 8) ? ((k >> 1) * 4 + (k & 1)) : (((k - 8) >> 1) * 4 + 2 + (k & 1));
}
__device__ __forceinline__ int pidx32h(int a) {
    return (a & 16) + pidx16(a & 15);
}
// bank swizzle of 8B-unit index by row index p (conflict-free frag loads)
__device__ __forceinline__ int swz(int p) {
    int t = (p >> 1) & 3;
    return t ^ ((t & 1) << 2);
}

#define MBAR_INIT(a, c) \
    asm volatile("mbarrier.init.shared.b64 [%0], %1;" :: "r"((uint32_t)(a)), "r"((uint32_t)(c)) : "memory")
#define MBAR_EXPECT(a, bytes) \
    asm volatile("mbarrier.arrive.expect_tx.shared.b64 _, [%0], %1;" :: "r"((uint32_t)(a)), "r"((uint32_t)(bytes)) : "memory")
#define MBAR_WAIT(a, p) do {                                                         \
    uint32_t _m = (uint32_t)(a), _p = (uint32_t)(p), _d;                             \
    asm volatile("{\n\t.reg .pred q;\n\t"                                            \
        "mbarrier.try_wait.parity.acquire.cta.shared::cta.b64 q, [%1], %2;\n\t"      \
        "selp.b32 %0, 1, 0, q;\n\t}" : "=r"(_d) : "r"(_m), "r"(_p) : "memory");      \
    if (!_d) {                                                                       \
        asm volatile("{\n\t.reg .pred Q;\n\tWL_%=:\n\t"                              \
            "mbarrier.try_wait.parity.acquire.cta.shared::cta.b64 Q, [%0], %1, 0x989680;\n\t" \
            "@Q bra.uni WD_%=;\n\tbra.uni WL_%=;\n\tWD_%=:\n\t}"                     \
            :: "r"(_m), "r"(_p) : "memory");                                         \
    }                                                                                \
} while (0)

__device__ __forceinline__ void bulk_cp(uint32_t dst, const void* src, uint32_t bytes, uint32_t mbar) {
    asm volatile(
        "cp.async.bulk.shared::cluster.global.mbarrier::complete_tx::bytes [%0], [%1], %2, [%3];"
        :: "r"(dst), "l"(src), "r"(bytes), "r"(mbar) : "memory");
}

// ---------------- kdummy: profiling alignment no-op ----------------
__global__ void kdummy() {}

// ---------------- kP: NCHW -> chunk-major padded fp16, k-permuted + bank-swizzled ----------------
__global__ void kP(const float* __restrict__ x) {
    __shared__ float t[32][33];
    int n = blockIdx.z, h = blockIdx.y, w0 = blockIdx.x * 32;
    int tid = threadIdx.x;
    int a = tid & 31, b = tid >> 5;  // b: 0..7
    int pc = pidx32h(a);
    int e = pc >> 2, hf = pc & 3;
    for (int c0 = 0; c0 < CIN; c0 += 32) {
        int ch = c0 >> 5;
        __syncthreads();
#pragma unroll
        for (int j = 0; j < 4; j++) {
            int c = c0 + b + j * 8;
            t[b + j * 8][a] = x[(((size_t)n * CIN + c) * HH + h) * WW + w0 + a];
        }
        __syncthreads();
#pragma unroll
        for (int j = 0; j < 4; j++) {
            int wp = w0 + b + j * 8 + 1;
            int ep = e ^ swz(wp);
            size_t idx = ((((size_t)n * 8 + ch) * PW + (h + 1)) * PW + wp) * 32 + ep * 4 + hf;
            sc_pad[idx] = __float2half_rn(t[a][b + j * 8]);
        }
    }
}

// ---------------- kW: W[oc][ci][3][3] -> Wp[chunk][tap][oc][swizzled 32] ----------------
__global__ void kW(const float* __restrict__ W) {
    int bi = blockIdx.x;            // 0..2303
    int oc = bi & 255, tap = bi >> 8;
    int ci = threadIdx.x;
    int ch = ci >> 5, c32 = ci & 31;
    int pc = pidx32h(c32);
    int ep = (pc >> 2) ^ swz(oc & 7);
    sc_Wp[(((size_t)ch * 9 + tap) * OCB + oc) * 32 + ep * 4 + (pc & 3)] =
        __float2half_rn(W[((size_t)oc * CIN + ci) * 9 + tap]);
}

// ---------------- kconv: fp16 m16n8k16, bulk-copy staged, conflict-free frags ----------------
// CTA: 256 thr, 8 warps (wm 0..3 x wn 0..1). Tile M=256 (2 out rows) x N=128 oc.
// Stage = one ci-chunk: A[4 rows][130][64B] (4x8320B) + B[9 taps][128 oc][64B] (9x8192B)
#define A_ROW_H   4160          // halves per A row (130*32)
#define A_H       16640         // halves per A tile (4 rows)
#define B_TAP_H   4096          // halves per B tap (128*32)
#define STAGE_H   53504         // halves per stage (A_H + 9*B_TAP_H)
#define STAGE_BYTES 107008u
#define MBAR_OFF  214016u
#define CONV_SMEM 214048

__device__ __forceinline__ void issue_bulk(const __half* __restrict__ padn,
                                           const __half* __restrict__ wpn,
                                           int h0, int by, int ch,
                                           uint32_t smbase, int buf, uint32_t mbar) {
    MBAR_EXPECT(mbar, STAGE_BYTES);
    uint32_t dst = smbase + (uint32_t)buf * STAGE_BYTES;
    const __half* asrc = padn + ((size_t)ch * PW + h0) * (PW * 32);
#pragma unroll
    for (int r = 0; r < 4; r++)
        bulk_cp(dst + r * 8320u, asrc + (size_t)r * A_ROW_H, 8320u, mbar);
    const __half* bsrc = wpn + (((size_t)ch * 9) * OCB + by * 128) * 32;
#pragma unroll
    for (int tp = 0; tp < 9; tp++)
        bulk_cp(dst + 33280u + tp * 8192u, bsrc + (size_t)tp * OCB * 32, 8192u, mbar);
}

__global__ void __launch_bounds__(256, 1) kconv(const float* __restrict__ pb) {
    extern __shared__ __half smh[];
    uint32_t smbase = smem_u32(smh);
    int tid = threadIdx.x, lane = tid & 31;
    int wid = tid >> 5;
    int wm = wid & 3, wn = wid >> 2;
    int s = blockIdx.x;
    int n = s >> 6, h0 = (s & 63) * 2;
    int by = blockIdx.y;
    const __half* padn = sc_pad + (size_t)n * 8 * PW * PW * 32;

    float acc[4][8][4];
#pragma unroll
    for (int a = 0; a < 4; a++)
#pragma unroll
        for (int b = 0; b < 8; b++)
#pragma unroll
            for (int c = 0; c < 4; c++) acc[a][b][c] = 0.f;

    int mrow = lane >> 2, kc = lane & 3;
    int ro = wm >> 1;                         // out-row offset 0..1
    int pbase = (wm & 1) * 64 + mrow;         // + mf*16 + dx
    int brow = wn * 64 + mrow;                // + nf*8
    int xB = swz(mrow);

    uint32_t mb0 = smbase + MBAR_OFF, mb1 = mb0 + 8;
    if (tid == 0) {
        MBAR_INIT(mb0, 1);
        MBAR_INIT(mb1, 1);
    }
    __syncthreads();
    if (tid == 0) {
        issue_bulk(padn, sc_Wp, h0, by, 0, smbase, 0, mb0);
        issue_bulk(padn, sc_Wp, h0, by, 1, smbase, 1, mb1);
    }

#pragma unroll 1
    for (int st = 0; st < 8; st++) {
        MBAR_WAIT(st & 1 ? mb1 : mb0, (st >> 1) & 1);

        const __half* A = smh + (st & 1) * STAGE_H;
        const __half* B = A + A_H;
#pragma unroll
        for (int dy = 0; dy < 3; dy++) {
            const __half* Arow = A + (ro + dy) * A_ROW_H;
#pragma unroll
            for (int dx = 0; dx < 3; dx++) {
                int xA = swz((mrow + dx) & 7);
                const __half* Bt = B + (dy * 3 + dx) * B_TAP_H;
#pragma unroll
                for (int ks = 0; ks < 2; ks++) {
                    int eA = ((ks * 4 + kc) ^ xA) * 4;
                    int eB = ((ks * 4 + kc) ^ xB) * 4;
                    uint32_t af[4][4];
#pragma unroll
                    for (int mf = 0; mf < 4; mf++) {
                        int p = pbase + mf * 16 + dx;
                        const uint2* plo = (const uint2*)(Arow + p * 32 + eA);
                        uint2 lo = plo[0];
                        uint2 hi = *(const uint2*)((const __half*)plo + 256);  // p+8
                        af[mf][0] = lo.x;
                        af[mf][1] = hi.x;
                        af[mf][2] = lo.y;
                        af[mf][3] = hi.y;
                    }
                    uint32_t bfr[8][2];
#pragma unroll
                    for (int nf = 0; nf < 8; nf++) {
                        uint2 bv = *(const uint2*)(Bt + (brow + nf * 8) * 32 + eB);
                        bfr[nf][0] = bv.x;
                        bfr[nf][1] = bv.y;
                    }
#pragma unroll
                    for (int mf = 0; mf < 4; mf++)
#pragma unroll
                        for (int nf = 0; nf < 8; nf++)
                            asm volatile(
                                "mma.sync.aligned.m16n8k16.row.col.f32.f16.f16.f32 "
                                "{%0,%1,%2,%3}, {%4,%5,%6,%7}, {%8,%9}, {%0,%1,%2,%3};"
                                : "+f"(acc[mf][nf][0]), "+f"(acc[mf][nf][1]),
                                  "+f"(acc[mf][nf][2]), "+f"(acc[mf][nf][3])
                                : "r"(af[mf][0]), "r"(af[mf][1]), "r"(af[mf][2]), "r"(af[mf][3]),
                                  "r"(bfr[nf][0]), "r"(bfr[nf][1]));
                }
            }
        }
        __syncthreads();
        if (st + 2 < 8 && tid == 0)
            issue_bulk(padn, sc_Wp, h0, by, st + 2, smbase, st & 1, st & 1 ? mb1 : mb0);
    }

    // epilogue: bias + fast mish -> fp16 sc_base NCHW, plus deterministic BN partials
    int h = h0 + ro;
    float ssum[8][2], ssq[8][2];
#pragma unroll
    for (int nf = 0; nf < 8; nf++) {
        ssum[nf][0] = ssum[nf][1] = 0.f;
        ssq[nf][0] = ssq[nf][1] = 0.f;
    }
#pragma unroll
    for (int mf = 0; mf < 4; mf++) {
        int w = (wm & 1) * 64 + mf * 16 + mrow;
#pragma unroll
        for (int nf = 0; nf < 8; nf++) {
            int oc = by * 128 + wn * 64 + nf * 8 + 2 * kc;
            float b0v = pb[oc], b1v = pb[oc + 1];
            float v0 = mishf(acc[mf][nf][0] + b0v);
            float v1 = mishf(acc[mf][nf][1] + b1v);
            float v2 = mishf(acc[mf][nf][2] + b0v);
            float v3 = mishf(acc[mf][nf][3] + b1v);
            __half* p = sc_base + ((size_t)(n * OCB + oc)) * HWSZ + h * WW + w;
            p[0] = __float2half_rn(v0);
            p[HWSZ] = __float2half_rn(v1);
            p[8] = __float2half_rn(v2);
            p[HWSZ + 8] = __float2half_rn(v3);
            ssum[nf][0] += v0 + v2;  ssq[nf][0] += v0 * v0 + v2 * v2;
            ssum[nf][1] += v1 + v3;  ssq[nf][1] += v1 * v1 + v3 * v3;
        }
    }
#pragma unroll
    for (int off = 4; off <= 16; off <<= 1) {
#pragma unroll
        for (int nf = 0; nf < 8; nf++)
#pragma unroll
            for (int j = 0; j < 2; j++) {
                ssum[nf][j] += __shfl_xor_sync(0xffffffffu, ssum[nf][j], off);
                ssq[nf][j] += __shfl_xor_sync(0xffffffffu, ssq[nf][j], off);
            }
    }
    float* part = (float*)smh;  // overlay [wn][wm][64 chl][2]
    __syncthreads();
    if (mrow == 0) {
#pragma unroll
        for (int nf = 0; nf < 8; nf++)
#pragma unroll
            for (int j = 0; j < 2; j++) {
                int chl = nf * 8 + 2 * kc + j;
                part[((wn * 4 + wm) * 64 + chl) * 2 + 0] = ssum[nf][j];
                part[((wn * 4 + wm) * 64 + chl) * 2 + 1] = ssq[nf][j];
            }
    }
    __syncthreads();
    {
        int wn2 = tid >> 7, chl = (tid >> 1) & 63, v = tid & 1;
        float t = 0.f;
#pragma unroll
        for (int wm2 = 0; wm2 < 4; wm2++)
            t += part[((wn2 * 4 + wm2) * 64 + chl) * 2 + v];
        sc_part[by * 128 + wn2 * 64 + chl][s][v] = t;
    }
}

// ---------------- K2: base BN stats from partials (deterministic fixed-order) ----------------
__global__ void k2_base_stats(const float* __restrict__ gam, const float* __restrict__ bet) {
    __shared__ float red[256];
    int c = blockIdx.x, tid = threadIdx.x;
    float s = sc_part[c][tid][0] + sc_part[c][tid + 256][0];
    float sum = block_reduce(s, red, tid);
    float q = sc_part[c][tid][1] + sc_part[c][tid + 256][1];
    float sq = block_reduce(q, red, tid);
    if (tid == 0) {
        float inv_n = 1.f / (float)(NB * HWSZ);
        float mean = sum * inv_n;
        float var = sq * inv_n - mean * mean;
        float inv = rsqrtf(var + BNEPS);
        float scl = gam[c] * inv;
        sc_scaleA[c] = scl;
        sc_shiftA[c] = bet[c] - mean * scl;
    }
}

// ---------------- K3: fold base BN into 1x1 conv weights ----------------
__global__ void k3_fold(const float* __restrict__ Wc, const float* __restrict__ bc,
                        const float* __restrict__ Wr, const float* __restrict__ br) {
    __shared__ float red[256];
    int o = blockIdx.x, ci = threadIdx.x;
    const float* Ws;
    float bs;
    int ol;
    if (o < NCLS) { Ws = Wc; ol = o; bs = bc[o]; }
    else { Ws = Wr; ol = o - NCLS; bs = br[ol]; }
    float w = Ws[ol * CIN + ci];
    sc_Wf[o * CIN + ci] = w * sc_scaleA[ci];
    float tot = block_reduce(w * sc_shiftA[ci], red, ci);
    if (ci == 0) sc_bf[o] = bs + tot;
}

// ---------------- K4m: merged 1x1 convs (cls+reg), fp16 reads, adjacent px ----------------
#define K4_SMEM (CIN * 56 * 4)
__global__ void __launch_bounds__(256) k4m() {
    extern __shared__ float swf[];
    int tid = threadIdx.x;
    for (int i = tid; i < CIN * 56; i += 256) {
        int c = i / 56, o = i - c * 56;
        swf[i] = (o < NTOT) ? sc_Wf[o * CIN + c] : 0.f;
    }
    __syncthreads();
    int pstart = blockIdx.x * 512;
    int n = pstart >> 14;
    int hw2 = (pstart & 16383) + 2 * tid;   // px at hw2, hw2+1 (adjacent)

    unsigned long long acc2[27][2];
#pragma unroll
    for (int op = 0; op < 27; op++) {
        unsigned long long b = pk2ab(sc_bf[2 * op], sc_bf[2 * op + 1]);
        acc2[op][0] = b;
        acc2[op][1] = b;
    }
    const __half* bpn = sc_base + (size_t)n * OCB * HWSZ + hw2;
#pragma unroll 1
    for (int c = 0; c < CIN; c += 8) {
        float2 f[8];
#pragma unroll
        for (int u = 0; u < 8; u++) {
            __half2 hv = *(const __half2*)(bpn + (size_t)(c + u) * HWSZ);
            f[u] = __half22float2(hv);
        }
#pragma unroll
        for (int u = 0; u < 8; u++) {
            unsigned long long p0 = pk2(f[u].x), p1 = pk2(f[u].y);
            const unsigned long long* wrow = (const unsigned long long*)(swf + (c + u) * 56);
#pragma unroll
            for (int op = 0; op < 27; op++) {
                unsigned long long w = wrow[op];
                fma2(acc2[op][0], w, p0);
                fma2(acc2[op][1], w, p1);
            }
        }
    }
#pragma unroll
    for (int op = 0; op < 27; op++) {
        float2 a = upk(acc2[op][0]);   // px0: (ch0, ch1)
        float2 b = upk(acc2[op][1]);   // px1: (ch0, ch1)
        int ch0 = 2 * op, ch1 = 2 * op + 1;
        if (ch0 < NCLS)
            *(float2*)(sc_cls + (size_t)(n * NCLS + ch0) * HWSZ + hw2) = make_float2(a.x, b.x);
        else
            *(float2*)(sc_reg + (size_t)(n * NREG + (ch0 - NCLS)) * HWSZ + hw2) = make_float2(a.x, b.x);
        if (ch1 < NCLS)
            *(float2*)(sc_cls + (size_t)(n * NCLS + ch1) * HWSZ + hw2) = make_float2(a.y, b.y);
        else
            *(float2*)(sc_reg + (size_t)(n * NREG + (ch1 - NCLS)) * HWSZ + hw2) = make_float2(a.y, b.y);
    }
}

// ---------------- K5: cls/reg BN stats ----------------
__global__ void k5_stats2(const float* __restrict__ gc, const float* __restrict__ bc,
                          const float* __restrict__ gr, const float* __restrict__ br) {
    __shared__ float red[256];
    int b = blockIdx.x, tid = threadIdx.x;
    const float* src;
    int nch, ch;
    float gam, bet;
    if (b < NCLS) { src = sc_cls; nch = NCLS; ch = b; gam = gc[ch]; bet = bc[ch]; }
    else { src = sc_reg; nch = NREG; ch = b - NCLS; gam = gr[ch]; bet = br[ch]; }
    float s = 0.f;
    for (int n = 0; n < NB; n++) {
        const float* p = &src[(size_t)(n * nch + ch) * HWSZ];
        for (int i = tid; i < HWSZ; i += 256) s += p[i];
    }
    float mean = block_reduce(s, red, tid) * (1.f / (NB * HWSZ));
    s = 0.f;
    for (int n = 0; n < NB; n++) {
        const float* p = &src[(size_t)(n * nch + ch) * HWSZ];
        for (int i = tid; i < HWSZ; i += 256) {
            float d = p[i] - mean;
            s += d * d;
        }
    }
    float var = block_reduce(s, red, tid) * (1.f / (NB * HWSZ));
    if (tid == 0) {
        float inv = rsqrtf(var + BNEPS);
        float scl = gam * inv;
        sc_s2[b] = scl;
        sc_h2[b] = bet - mean * scl;
    }
}

// ---------------- K6: softmax + anchor decode (fast math) ----------------
__constant__ float c_wa[9] = {455.f, 911.f, 1823.f, 319.f, 639.f, 1279.f, 223.f, 447.f, 895.f};
__constant__ float c_ha[9] = {223.f, 447.f, 895.f, 319.f, 639.f, 1279.f, 447.f, 895.f, 1791.f};

__global__ void k6_decode(const int* __restrict__ imgsz, float* __restrict__ out) {
    int t = blockIdx.x * 256 + threadIdx.x;
    if (t >= NB * HWSZ) return;
    int n = t >> 14, hw = t & 16383;
    int hy = hw >> 7, wx = hw & 127;
    float lim = 2048.f;
    if (imgsz) {
        int iv = *imgsz;
        lim = (iv > 0 && iv < (1 << 24)) ? (float)iv : __int_as_float(iv);
    }
    float cls[NCLS], rg[NREG];
#pragma unroll
    for (int o = 0; o < NCLS; o++)
        cls[o] = sc_cls[(size_t)(n * NCLS + o) * HWSZ + hw] * sc_s2[o] + sc_h2[o];
#pragma unroll
    for (int o = 0; o < NREG; o++)
        rg[o] = sc_reg[(size_t)(n * NREG + o) * HWSZ + hw] * sc_s2[NCLS + o] + sc_h2[NCLS + o];

    const size_t K = (size_t)HWSZ * 9;
    float* fg = out;
    float* ts = out + (size_t)NB * K;
    float* ro = ts + (size_t)NB * K * 4;
    size_t kb = (size_t)n * K + (size_t)hw * 9;

    float cxa = 19.5f + 16.f * (float)wx;
    float cya = 19.5f + 16.f * (float)hy;
#pragma unroll
    for (int a = 0; a < 9; a++) {
        float wa = c_wa[a], ha = c_ha[a];
        float x1 = fminf(fmaxf(rg[a * 4 + 0] + (cxa - 0.5f * wa), 0.f), lim);
        float y1 = fminf(fmaxf(rg[a * 4 + 1] + (cya - 0.5f * ha), 0.f), lim);
        float x2 = fminf(fmaxf(rg[a * 4 + 2] + (cxa + 0.5f * wa), 0.f), lim);
        float y2 = fminf(fmaxf(rg[a * 4 + 3] + (cya + 0.5f * ha), 0.f), lim);
        float w = x2 - x1, h = y2 - y1;
        float cx = x1 + 0.5f * w, cy = y1 + 0.5f * h;
        float s0 = cls[a * 2], s1 = cls[a * 2 + 1];
        fg[kb + a] = 1.f / (1.f + __expf(s0 - s1));
        size_t o4 = (kb + a) * 4;
        ts[o4 + 0] = (cx - cxa) / wa;
        ts[o4 + 1] = (cy - cya) / ha;
        ts[o4 + 2] = __logf(fmaxf(w / wa, 1e-30f));
        ts[o4 + 3] = __logf(fmaxf(h / ha, 1e-30f));
        ro[o4 + 0] = cx;
        ro[o4 + 1] = cy;
        ro[o4 + 2] = w;
        ro[o4 + 3] = h;
    }
}

// ---------------- launch ----------------
extern "C" void kernel_launch(void* const* d_in, const int* in_sizes, int n_in,
                              void* d_out, int out_size) {
    const float* x   = (const float*)d_in[0];
    const float* Wb  = (const float*)d_in[1];
    const float* bb  = (const float*)d_in[2];
    const float* gb  = (const float*)d_in[3];
    const float* beb = (const float*)d_in[4];
    const float* Wc  = (const float*)d_in[5];
    const float* bc  = (const float*)d_in[6];
    const float* gc  = (const float*)d_in[7];
    const float* bec = (const float*)d_in[8];
    const float* Wr  = (const float*)d_in[9];
    const float* br  = (const float*)d_in[10];
    const float* gr  = (const float*)d_in[11];
    const float* ber = (const float*)d_in[12];
    const int* imgsz = (n_in > 13) ? (const int*)d_in[13] : nullptr;
    float* out = (float*)d_out;

    static int smem_set = 0;
    if (!smem_set) {
        cudaFuncSetAttribute(kconv, cudaFuncAttributeMaxDynamicSharedMemorySize, CONV_SMEM);
        cudaFuncSetAttribute(k4m, cudaFuncAttributeMaxDynamicSharedMemorySize, K4_SMEM);
        smem_set = 1;
    }

    dim3 gp(4, 128, NB);
    kP<<<gp, 256>>>(x);                          // launch 0
    kW<<<9 * OCB, 256>>>(Wb);                    // launch 1
    kdummy<<<1, 32>>>();                         // launch 2 (aligns ncu capture onto kconv)

    dim3 gc2(512, 2);
    kconv<<<gc2, 256, CONV_SMEM>>>(bb);          // launch 3 <- profiled

    k2_base_stats<<<OCB, 256>>>(gb, beb);
    k3_fold<<<NTOT, 256>>>(Wc, bc, Wr, br);
    k4m<<<NB * HWSZ / 512, 256, K4_SMEM>>>();
    k5_stats2<<<NTOT, 256>>>(gc, bec, gr, ber);
    k6_decode<<<NB * HWSZ / 256, 256>>>(imgsz, out);
}